// round 3
// baseline (speedup 1.0000x reference)
#include <cuda_runtime.h>
#include <cuda_bf16.h>
#include <cstdint>
#include <cstddef>

#define T_STEPS 50000
#define DIM_D   768
#define DIM_F   128
#define GATES   512

// Scratch (no cudaMalloc allowed)
__device__ float g_pre2[T_STEPS * GATES];   // 102.4 MB
__device__ float g_hs2 [T_STEPS * DIM_F];   // 25.6 MB

// ---------------------------------------------------------------------------
// fp32 GEMM: C[M,N] = A[M,K] @ B[N,K]^T + bias1 (+bias2), optional sigmoid
// ---------------------------------------------------------------------------
template <int ACT>
__global__ __launch_bounds__(256)
void gemm_at_kernel(const float* __restrict__ A, const float* __restrict__ B,
                    const float* __restrict__ bias1, const float* __restrict__ bias2,
                    float* __restrict__ C, int M, int N, int K)
{
    __shared__ float As[16][68];
    __shared__ float Bs[16][68];
    const int tid = threadIdx.x;
    const int tx = tid & 15;
    const int ty = tid >> 4;
    const int row0 = blockIdx.y * 64;
    const int col0 = blockIdx.x * 64;

    float acc[4][4];
#pragma unroll
    for (int i = 0; i < 4; ++i)
#pragma unroll
        for (int jj = 0; jj < 4; ++jj) acc[i][jj] = 0.0f;

    for (int k0 = 0; k0 < K; k0 += 16) {
#pragma unroll
        for (int p = 0; p < 4; ++p) {
            int r = ty + p * 16;
            int gr = row0 + r;
            As[tx][r] = (gr < M) ? A[(size_t)gr * K + k0 + tx] : 0.0f;
            Bs[tx][r] = B[(size_t)(col0 + r) * K + k0 + tx];
        }
        __syncthreads();
#pragma unroll
        for (int k = 0; k < 16; ++k) {
            float a0 = As[k][ty * 4 + 0], a1 = As[k][ty * 4 + 1];
            float a2 = As[k][ty * 4 + 2], a3 = As[k][ty * 4 + 3];
            float b0 = Bs[k][tx * 4 + 0], b1 = Bs[k][tx * 4 + 1];
            float b2 = Bs[k][tx * 4 + 2], b3 = Bs[k][tx * 4 + 3];
            acc[0][0] += a0 * b0; acc[0][1] += a0 * b1; acc[0][2] += a0 * b2; acc[0][3] += a0 * b3;
            acc[1][0] += a1 * b0; acc[1][1] += a1 * b1; acc[1][2] += a1 * b2; acc[1][3] += a1 * b3;
            acc[2][0] += a2 * b0; acc[2][1] += a2 * b1; acc[2][2] += a2 * b2; acc[2][3] += a2 * b3;
            acc[3][0] += a3 * b0; acc[3][1] += a3 * b1; acc[3][2] += a3 * b2; acc[3][3] += a3 * b3;
        }
        __syncthreads();
    }

#pragma unroll
    for (int i = 0; i < 4; ++i) {
        int gr = row0 + ty * 4 + i;
        if (gr >= M) continue;
#pragma unroll
        for (int jj = 0; jj < 4; ++jj) {
            int gc = col0 + tx * 4 + jj;
            float v = acc[i][jj] + bias1[gc];
            if (bias2) v += bias2[gc];
            if (ACT) v = __fdividef(1.0f, 1.0f + __expf(-v));
            C[(size_t)gr * N + gc] = v;
        }
    }
}

// ---------------------------------------------------------------------------
// LSTM scan: single CTA, 256 threads (8 warps). Whh held in registers as
// bf16x2 mma.sync A-fragments. Per step:
//   gates = Whh @ h  via 256x mma.sync.m16n8k16 (only B/C column 0 is real),
//   then 128 threads do their own gate activations and state update.
// ---------------------------------------------------------------------------
__device__ __forceinline__ uint32_t pack2bf(float lo, float hi) {
    uint32_t r;
    asm("cvt.rn.bf16x2.f32 %0, %1, %2;" : "=r"(r) : "f"(hi), "f"(lo));
    return r;
}

__device__ __forceinline__ void mma16816(float c[4], const uint32_t a[4],
                                         uint32_t b0, uint32_t b1) {
    asm volatile(
        "mma.sync.aligned.m16n8k16.row.col.f32.bf16.bf16.f32 "
        "{%0,%1,%2,%3}, {%4,%5,%6,%7}, {%8,%9}, {%0,%1,%2,%3};"
        : "+f"(c[0]), "+f"(c[1]), "+f"(c[2]), "+f"(c[3])
        : "r"(a[0]), "r"(a[1]), "r"(a[2]), "r"(a[3]), "r"(b0), "r"(b1));
}

__device__ __forceinline__ float fast_sigmoid(float x) {
    return __fdividef(1.0f, 1.0f + __expf(-x));
}
__device__ __forceinline__ float fast_tanh(float x) {
    x = fminf(10.0f, fmaxf(-10.0f, x));
    float e = __expf(-2.0f * x);
    return __fdividef(1.0f - e, 1.0f + e);
}

__global__ __launch_bounds__(256, 1)
void lstm_scan_kernel(const float* __restrict__ pre2,
                      const float* __restrict__ Whh,
                      const float* __restrict__ h0,
                      const float* __restrict__ c0,
                      float* __restrict__ hs)
{
    __shared__ __align__(16) __nv_bfloat16 h_s[DIM_F];
    __shared__ float gates_s[GATES];

    const int tid  = threadIdx.x;
    const int wid  = tid >> 5;        // warp 0..7: gate rows [wid*64, wid*64+64)
    const int lane = tid & 31;
    const int grp  = lane >> 2;       // 0..7
    const int tig  = lane & 3;        // 0..3

    // ---- one-time: load Whh into mma A-fragments (bf16x2, 128 regs/thread) ----
    uint32_t A[4][8][4];
#pragma unroll
    for (int mt = 0; mt < 4; ++mt) {
        const int r0 = wid * 64 + mt * 16 + grp;
        const int r1 = r0 + 8;
#pragma unroll
        for (int kk = 0; kk < 8; ++kk) {
            const int cL = kk * 16 + tig * 2;
            const int cH = cL + 8;
            A[mt][kk][0] = pack2bf(Whh[r0 * DIM_F + cL], Whh[r0 * DIM_F + cL + 1]);
            A[mt][kk][1] = pack2bf(Whh[r1 * DIM_F + cL], Whh[r1 * DIM_F + cL + 1]);
            A[mt][kk][2] = pack2bf(Whh[r0 * DIM_F + cH], Whh[r0 * DIM_F + cH + 1]);
            A[mt][kk][3] = pack2bf(Whh[r1 * DIM_F + cH], Whh[r1 * DIM_F + cH + 1]);
        }
    }

    // ---- init state (threads 0..127 own hidden unit j = tid) ----
    float cst = 0.0f, p0 = 0.0f, p1 = 0.0f, p2 = 0.0f, p3 = 0.0f;
    if (tid < DIM_F) {
        cst = c0[tid];
        h_s[tid] = __float2bfloat16(h0[tid]);
        p0 = pre2[tid];
        p1 = pre2[DIM_F + tid];
        p2 = pre2[2 * DIM_F + tid];
        p3 = pre2[3 * DIM_F + tid];
    }
    __syncthreads();

    const uint32_t* h32 = reinterpret_cast<const uint32_t*>(h_s);

#pragma unroll 1
    for (int t = 0; t < T_STEPS; ++t) {
        // ---- B fragments: broadcast loads of current h (all lanes mirror col 0) ----
        uint32_t B0[8], B1[8];
#pragma unroll
        for (int kk = 0; kk < 8; ++kk) {
            B0[kk] = h32[kk * 8 + tig];
            B1[kk] = h32[kk * 8 + 4 + tig];
        }

        // ---- prefetch next step's pre2 (hidden under the MMA chain) ----
        float q0 = 0.f, q1 = 0.f, q2 = 0.f, q3 = 0.f;
        if (tid < DIM_F && t + 1 < T_STEPS) {
            const float* pn = pre2 + (size_t)(t + 1) * GATES;
            q0 = pn[tid]; q1 = pn[DIM_F + tid];
            q2 = pn[2 * DIM_F + tid]; q3 = pn[3 * DIM_F + tid];
        }

        // ---- 32 MMAs: 4 m-tiles x 8 k-chunks, f32 accumulate ----
        float C0[4], C1[4], C2[4], C3[4];
#pragma unroll
        for (int i = 0; i < 4; ++i) { C0[i] = 0.f; C1[i] = 0.f; C2[i] = 0.f; C3[i] = 0.f; }
#pragma unroll
        for (int kk = 0; kk < 8; ++kk) {
            mma16816(C0, A[0][kk], B0[kk], B1[kk]);
            mma16816(C1, A[1][kk], B0[kk], B1[kk]);
            mma16816(C2, A[2][kk], B0[kk], B1[kk]);
            mma16816(C3, A[3][kk], B0[kk], B1[kk]);
        }

        // ---- column 0 of C holds the real gates: lanes with tig==0 ----
        if (tig == 0) {
            const int base = wid * 64;
            gates_s[base +  0 + grp] = C0[0];
            gates_s[base +  8 + grp] = C0[2];
            gates_s[base + 16 + grp] = C1[0];
            gates_s[base + 24 + grp] = C1[2];
            gates_s[base + 32 + grp] = C2[0];
            gates_s[base + 40 + grp] = C2[2];
            gates_s[base + 48 + grp] = C3[0];
            gates_s[base + 56 + grp] = C3[2];
        }
        __syncthreads();

        // ---- activations + state update (threads 0..127) ----
        if (tid < DIM_F) {
            float gi = gates_s[tid]             + p0;
            float gf = gates_s[DIM_F + tid]     + p1;
            float gg = gates_s[2 * DIM_F + tid] + p2;
            float go = gates_s[3 * DIM_F + tid] + p3;

            float ai = fast_sigmoid(gi);
            float af = fast_sigmoid(gf);
            float ag = fast_tanh(gg);
            float ao = fast_sigmoid(go);

            cst = af * cst + ai * ag;
            float hv = ao * fast_tanh(cst);

            hs[(size_t)t * DIM_F + tid] = hv;
            h_s[tid] = __float2bfloat16(hv);
            p0 = q0; p1 = q1; p2 = q2; p3 = q3;
        }
        __syncthreads();
    }
}

// ---------------------------------------------------------------------------
extern "C" void kernel_launch(void* const* d_in, const int* in_sizes, int n_in,
                              void* d_out, int out_size)
{
    // metadata order: x,h1,c1,h2,c2,Wih1,Whh1,bih1,bhh1,Wih2,Whh2,bih2,bhh2,Wfc,bfc
    const float* x    = (const float*)d_in[0];
    const float* h2   = (const float*)d_in[3];
    const float* c2   = (const float*)d_in[4];
    const float* Wih2 = (const float*)d_in[9];
    const float* Whh2 = (const float*)d_in[10];
    const float* bih2 = (const float*)d_in[11];
    const float* bhh2 = (const float*)d_in[12];
    const float* Wfc  = (const float*)d_in[13];
    const float* bfc  = (const float*)d_in[14];
    float* out = (float*)d_out;

    float* pre2 = nullptr;
    float* hs2  = nullptr;
    cudaGetSymbolAddress((void**)&pre2, g_pre2);
    cudaGetSymbolAddress((void**)&hs2,  g_hs2);

    // lstm1 is dead code: its output is discarded and nothing reads its state.

    // 1) pre2 = x @ Wih2^T + (bih2 + bhh2)
    dim3 g1(GATES / 64, (T_STEPS + 63) / 64);
    gemm_at_kernel<0><<<g1, 256>>>(x, Wih2, bih2, bhh2, pre2, T_STEPS, GATES, DIM_D);

    // 2) sequential LSTM scan (single CTA, register-resident weights + mma.sync)
    lstm_scan_kernel<<<1, 256>>>(pre2, Whh2, h2, c2, hs2);

    // 3) out = sigmoid(hs2 @ Wfc^T + bfc)
    dim3 g3(DIM_F / 64, (T_STEPS + 63) / 64);
    gemm_at_kernel<1><<<g3, 256>>>(hs2, Wfc, bfc, nullptr, out, T_STEPS, DIM_F, DIM_F);
}